// round 5
// baseline (speedup 1.0000x reference)
#include <cuda_runtime.h>

// HistogramLayer inference:
//   hist_probs[b,d] = freq[b,d] / sum_b freq[b,d]
//   bin[r,d] = clip(searchsorted_right(edges[:,d], x[r,d]) - 1, 0, 7)
//   out[r] = prod_d hist_probs[bin[r,d], d]
//
// Edges are base[b]*scale[d], base = integers -4..4. edges[8][d] = 4*scale
// exactly, so with u = (b-4)/4 (exact quarter-integer), the reference edge is
// round(u * e8): ONE fp32 rounding that we reproduce with __fmul_rn. The
// explicit-rounding intrinsics are load-bearing: without them the compiler
// contracts (u*e8) into the following subtraction's FMA and compares x against
// the UNROUNDED edge, misbinning x's within 1 ulp of an edge (seen as the
// rel_err bump in R3).
//
// Bin = arithmetic guess (FMA + floor) + exact +-1 correction vs the rounded
// edges. Probabilities gathered pairwise from a 2KB table of p[2p][b0]*p[2p+1][b1].

#define HD  16   // features
#define HNB 8    // bins
#define RPT 8    // rows per thread

__device__ __forceinline__ int find_bin(float xv, float inv, float e8)
{
    // guess: floor(x/scale + 4)  (inv approximate; errors fixed below)
    const float t  = fmaf(xv, inv, 4.0f);
    const float tf = floorf(t);
    int b = (int)tf;                                 // exact (tf integral)
    const float u  = fmaf(tf, 0.25f, -1.0f);         // (b-4)/4, exact
    const float elo = __fmul_rn(u, e8);              // == reference edge[b]
    const float ehi = __fmul_rn(u + 0.25f, e8);      // == reference edge[b+1]
    // searchsorted side="right": want elo <= x < ehi.
    // shi = 1 iff x <  ehi ; slo = 1 iff x < elo  (sign-bit arithmetic,
    // x == edge gives +0 -> goes right, matching the reference).
    const int shi = (int)(__float_as_uint(__fadd_rn(xv, -ehi)) >> 31);
    const int slo = (int)(__float_as_uint(__fadd_rn(xv, -elo)) >> 31);
    b += 1 - shi - slo;
    return max(0, min(HNB - 1, b));
}

__global__ __launch_bounds__(256, 6)
void HistogramLayer_13048110645959_kernel(
    const float* __restrict__ inputs,   // [B, 16]
    const float* __restrict__ freq,     // [8, 16]
    const float* __restrict__ edges,    // [9, 16]
    float* __restrict__ out,            // [B]
    int B)
{
    __shared__ float s_prob[HD * HNB];        // [d][b]
    __shared__ float s_pair[(HD / 2) * 64];   // [pair][b0][b1], 2 KB

    const int tid = threadIdx.x;

    // stage 1: normalized probabilities
    if (tid < HD * HNB) {
        const int d = tid >> 3;
        const int b = tid & 7;
        float s = 0.f;
        #pragma unroll
        for (int k = 0; k < HNB; ++k) s += freq[k * HD + d];
        s_prob[d * HNB + b] = freq[b * HD + d] / s;
    }
    __syncthreads();
    // stage 2: pairwise products
    #pragma unroll
    for (int i = tid; i < (HD / 2) * 64; i += 256) {
        const int p  = i >> 6;
        const int b0 = (i >> 3) & 7;
        const int b1 = i & 7;
        s_pair[i] = s_prob[(2 * p) * HNB + b0] * s_prob[(2 * p + 1) * HNB + b1];
    }
    __syncthreads();

    // per-feature constants (thread-uniform -> uniform registers)
    float e8[HD], inv[HD];
    #pragma unroll
    for (int d = 0; d < HD; ++d) {
        e8[d]  = edges[8 * HD + d];            // = 4*scale exactly
        inv[d] = __fdividef(4.0f, e8[d]);      // ~1/scale (errors corrected)
    }

    // grid-stride over rows: every thread does exactly RPT (guarded)
    // iterations -> perfect wave balance, no tail block.
    const int stride = gridDim.x * blockDim.x;
    int row = blockIdx.x * blockDim.x + tid;

    #pragma unroll
    for (int r = 0; r < RPT; ++r, row += stride) {
        if (row >= B) break;

        const float4* in4 = reinterpret_cast<const float4*>(inputs + (size_t)row * HD);
        const float4 v0 = in4[0];
        const float4 v1 = in4[1];
        const float4 v2 = in4[2];
        const float4 v3 = in4[3];

        float x[HD];
        x[0]=v0.x;  x[1]=v0.y;  x[2]=v0.z;  x[3]=v0.w;
        x[4]=v1.x;  x[5]=v1.y;  x[6]=v1.z;  x[7]=v1.w;
        x[8]=v2.x;  x[9]=v2.y;  x[10]=v2.z; x[11]=v2.w;
        x[12]=v3.x; x[13]=v3.y; x[14]=v3.z; x[15]=v3.w;

        float prod0 = 1.0f, prod1 = 1.0f;
        #pragma unroll
        for (int p = 0; p < HD / 2; ++p) {
            const int d0 = 2 * p, d1 = 2 * p + 1;
            const int b0 = find_bin(x[d0], inv[d0], e8[d0]);
            const int b1 = find_bin(x[d1], inv[d1], e8[d1]);
            const float pp = s_pair[(p << 6) + (b0 << 3) + b1];
            if (p & 1) prod1 *= pp; else prod0 *= pp;
        }
        out[row] = prod0 * prod1;
    }
}

extern "C" void kernel_launch(void* const* d_in, const int* in_sizes, int n_in,
                              void* d_out, int out_size)
{
    // Identify tensors by element count:
    //   inputs: B*16 (large), frequencies: 8*16=128, edges: 9*16=144.
    const float* inputs = nullptr;
    const float* freq   = nullptr;
    const float* edges  = nullptr;
    int B = 0;
    for (int i = 0; i < n_in; ++i) {
        if (in_sizes[i] == HNB * HD)            freq   = (const float*)d_in[i];
        else if (in_sizes[i] == (HNB + 1) * HD) edges  = (const float*)d_in[i];
        else { inputs = (const float*)d_in[i];  B = in_sizes[i] / HD; }
    }

    float* out = (float*)d_out;
    const int rows_per_block = 256 * RPT;
    const int blocks = (B + rows_per_block - 1) / rows_per_block;
    HistogramLayer_13048110645959_kernel<<<blocks, 256>>>(inputs, freq, edges, out, B);
}